// round 7
// baseline (speedup 1.0000x reference)
#include <cuda_runtime.h>
#include <cstddef>

#define D_DIM   64
#define N_USERS 4096
#define N_ITEMS 16384
#define L_U     50
#define L_I     20
#define OUT_W   (D_DIM + 2)   // 66
#define N_ROWS  (N_USERS + N_ITEMS)
#define B       10            // gathers per pipeline stage

// One warp per row; lane l owns columns 2l, 2l+1.
// Two-stage register pipeline: batch c+1 is issued before batch c is consumed,
// keeping ~2*B gathers (5KB/warp) in flight. __launch_bounds__(256,3) grants
// ~85 regs/thread so the g[2][B] staging (40 f32 regs) survives ptxas.
template <int L, bool IS_USER>
__device__ __forceinline__
void do_row(const float* __restrict__ emb,
            const float* __restrict__ w,
            float                     bias,
            const float* __restrict__ h1,
            const int*   __restrict__ my_idx,
            float*       __restrict__ orow,
            int lane)
{
    static_assert(L % B == 0, "L must be a multiple of B");
    constexpr int NC = L / B;

    int idx_lo = (L >= 32 || lane < L) ? my_idx[lane] : 0;
    int idx_hi = 0;
    if (L > 32) idx_hi = (lane + 32 < L) ? my_idx[lane + 32] : 0;

    float wsum = 0.f;
    if (L >= 32 || lane < L) wsum += __ldg(&w[idx_lo]);
    if (L > 32 && lane + 32 < L) wsum += __ldg(&w[idx_hi]);

    float2 g[2][B];

    auto issue = [&](int c, int buf) {
        #pragma unroll
        for (int k = 0; k < B; ++k) {
            const int j = c * B + k;
            int src = (L <= 32 || j < 32) ? idx_lo : idx_hi;
            int r   = __shfl_sync(0xffffffffu, src, j & 31);
            g[buf][k] = *reinterpret_cast<const float2*>(
                            emb + (size_t)r * D_DIM + 2 * lane);
        }
    };

    float sx = 0.f, sy = 0.f, qx = 0.f, qy = 0.f;

    auto consume = [&](int buf) {
        #pragma unroll
        for (int k = 0; k < B; ++k) {
            float2 v = g[buf][k];
            sx += v.x; sy += v.y;
            qx += v.x * v.x; qy += v.y * v.y;
        }
    };

    issue(0, 0);
    #pragma unroll
    for (int c = 0; c < NC; ++c) {
        if (c + 1 < NC) issue(c + 1, (c + 1) & 1);
        consume(c & 1);
    }

    float2 h = *reinterpret_cast<const float2*>(h1 + 2 * lane);
    float part = 0.5f * (sx * sx - qx) * h.x
               + 0.5f * (sy * sy - qy) * h.y + wsum;

    #pragma unroll
    for (int o = 16; o > 0; o >>= 1)
        part += __shfl_xor_sync(0xffffffffu, part, o);

    float2 sv; sv.x = sx; sv.y = sy;
    *reinterpret_cast<float2*>(orow + 2 * lane) = sv;   // stride 66 even -> 8B aligned

    if (lane == 0) {
        if (IS_USER) {
            orow[D_DIM]     = part + bias;
            orow[D_DIM + 1] = 1.0f;
        } else {
            orow[D_DIM]     = 1.0f;
            orow[D_DIM + 1] = part;
        }
    }
}

__global__ __launch_bounds__(256, 3)
void fm_fused_kernel(const float* __restrict__ uemb,
                     const float* __restrict__ iemb,
                     const float* __restrict__ uw,
                     const float* __restrict__ iw,
                     const float* __restrict__ gbias,
                     const float* __restrict__ h1,
                     const float* __restrict__ h2,
                     const int*   __restrict__ uidx,
                     const int*   __restrict__ iidx,
                     float*       __restrict__ out)
{
    const int lane = threadIdx.x & 31;
    const int gw   = (blockIdx.x * blockDim.x + threadIdx.x) >> 5;

    if (blockIdx.x == 0 && threadIdx.x < D_DIM) {
        out[(size_t)N_ROWS * OUT_W + threadIdx.x] = h2[threadIdx.x];
    }

    if (gw < N_USERS) {
        do_row<L_U, true>(uemb, uw, gbias[0], h1,
                          uidx + (size_t)gw * L_U,
                          out + (size_t)gw * OUT_W, lane);
    } else if (gw < N_ROWS) {
        const int row = gw - N_USERS;
        do_row<L_I, false>(iemb, iw, 0.f, h1,
                           iidx + (size_t)row * L_I,
                           out + (size_t)(N_USERS + row) * OUT_W, lane);
    }
}

extern "C" void kernel_launch(void* const* d_in, const int* in_sizes, int n_in,
                              void* d_out, int out_size)
{
    const float* uemb  = (const float*)d_in[0];
    const float* iemb  = (const float*)d_in[1];
    const float* uw    = (const float*)d_in[2];
    const float* iw    = (const float*)d_in[3];
    const float* gbias = (const float*)d_in[4];
    const float* h1    = (const float*)d_in[5];
    const float* h2    = (const float*)d_in[6];
    const int*   uidx  = (const int*)d_in[7];
    const int*   iidx  = (const int*)d_in[8];

    float* out = (float*)d_out;

    const int threads = 256;
    const int warps_per_block = threads / 32;
    const int blocks = (N_ROWS + warps_per_block - 1) / warps_per_block;

    fm_fused_kernel<<<blocks, threads>>>(uemb, iemb, uw, iw, gbias, h1, h2,
                                         uidx, iidx, out);
}

// round 8
// speedup vs baseline: 1.0924x; 1.0924x over previous
#include <cuda_runtime.h>
#include <cstddef>
#include <cstdint>

#define D_DIM   64
#define N_USERS 4096
#define N_ITEMS 16384
#define L_U     50
#define L_I     20
#define OUT_W   (D_DIM + 2)   // 66
#define N_ROWS  (N_USERS + N_ITEMS)

// Packed f32x2 helpers (Blackwell packed-f32 pipe; ptxas never auto-fuses these)
__device__ __forceinline__ void addx2(unsigned long long& acc, unsigned long long v) {
    asm("add.rn.f32x2 %0, %0, %1;" : "+l"(acc) : "l"(v));
}
__device__ __forceinline__ void fmax2(unsigned long long& acc, unsigned long long v) {
    asm("fma.rn.f32x2 %0, %1, %1, %0;" : "+l"(acc) : "l"(v));
}

// One warp per row; lane l owns columns 2l, 2l+1 (one float2 = one packed b64).
// Per gathered element: LDG.64 + SHFL + add.f32x2 + fma.f32x2  (4 issue slots).
template <int L, bool IS_USER>
__device__ __forceinline__
void do_row(const float* __restrict__ emb,
            const float* __restrict__ w,
            float                     bias,
            const float* __restrict__ h1,
            const int*   __restrict__ my_idx,
            float*       __restrict__ orow,
            int lane)
{
    int idx_lo = (L >= 32 || lane < L) ? my_idx[lane] : 0;
    int idx_hi = 0;
    if (L > 32) idx_hi = (lane + 32 < L) ? my_idx[lane + 32] : 0;

    float wsum = 0.f;
    if (L >= 32 || lane < L) wsum += __ldg(&w[idx_lo]);
    if (L > 32 && lane + 32 < L) wsum += __ldg(&w[idx_hi]);

    unsigned long long s01 = 0ull;   // packed (sx, sy)
    unsigned long long q01 = 0ull;   // packed (qx, qy)

    #pragma unroll
    for (int j = 0; j < L; ++j) {
        int src = (L <= 32 || j < 32) ? idx_lo : idx_hi;
        int r   = __shfl_sync(0xffffffffu, src, j & 31);
        unsigned long long v = *reinterpret_cast<const unsigned long long*>(
                                   emb + (size_t)r * D_DIM + 2 * lane);
        addx2(s01, v);
        fmax2(q01, v);
    }

    float sx = __uint_as_float((unsigned)(s01 & 0xffffffffull));
    float sy = __uint_as_float((unsigned)(s01 >> 32));
    float qx = __uint_as_float((unsigned)(q01 & 0xffffffffull));
    float qy = __uint_as_float((unsigned)(q01 >> 32));

    float2 h = *reinterpret_cast<const float2*>(h1 + 2 * lane);
    float part = 0.5f * (sx * sx - qx) * h.x
               + 0.5f * (sy * sy - qy) * h.y + wsum;

    #pragma unroll
    for (int o = 16; o > 0; o >>= 1)
        part += __shfl_xor_sync(0xffffffffu, part, o);

    float2 sv; sv.x = sx; sv.y = sy;
    *reinterpret_cast<float2*>(orow + 2 * lane) = sv;  // stride 66 even -> 8B aligned

    if (lane == 0) {
        if (IS_USER) {
            orow[D_DIM]     = part + bias;
            orow[D_DIM + 1] = 1.0f;
        } else {
            orow[D_DIM]     = 1.0f;
            orow[D_DIM + 1] = part;
        }
    }
}

__global__ __launch_bounds__(256)
void fm_fused_kernel(const float* __restrict__ uemb,
                     const float* __restrict__ iemb,
                     const float* __restrict__ uw,
                     const float* __restrict__ iw,
                     const float* __restrict__ gbias,
                     const float* __restrict__ h1,
                     const float* __restrict__ h2,
                     const int*   __restrict__ uidx,
                     const int*   __restrict__ iidx,
                     float*       __restrict__ out)
{
    const int lane = threadIdx.x & 31;
    const int gw   = (blockIdx.x * blockDim.x + threadIdx.x) >> 5;

    if (blockIdx.x == 0 && threadIdx.x < D_DIM) {
        out[(size_t)N_ROWS * OUT_W + threadIdx.x] = h2[threadIdx.x];
    }

    if (gw < N_USERS) {
        do_row<L_U, true>(uemb, uw, gbias[0], h1,
                          uidx + (size_t)gw * L_U,
                          out + (size_t)gw * OUT_W, lane);
    } else if (gw < N_ROWS) {
        const int row = gw - N_USERS;
        do_row<L_I, false>(iemb, iw, 0.f, h1,
                           iidx + (size_t)row * L_I,
                           out + (size_t)(N_USERS + row) * OUT_W, lane);
    }
}

extern "C" void kernel_launch(void* const* d_in, const int* in_sizes, int n_in,
                              void* d_out, int out_size)
{
    const float* uemb  = (const float*)d_in[0];
    const float* iemb  = (const float*)d_in[1];
    const float* uw    = (const float*)d_in[2];
    const float* iw    = (const float*)d_in[3];
    const float* gbias = (const float*)d_in[4];
    const float* h1    = (const float*)d_in[5];
    const float* h2    = (const float*)d_in[6];
    const int*   uidx  = (const int*)d_in[7];
    const int*   iidx  = (const int*)d_in[8];

    float* out = (float*)d_out;

    const int threads = 256;
    const int warps_per_block = threads / 32;
    const int blocks = (N_ROWS + warps_per_block - 1) / warps_per_block;

    fm_fused_kernel<<<blocks, threads>>>(uemb, iemb, uw, iw, gbias, h1, h2,
                                         uidx, iidx, out);
}